// round 14
// baseline (speedup 1.0000x reference)
#include <cuda_runtime.h>
#include <cuda_bf16.h>

#define BATCH    8
#define NVERTS   468
#define NTRI     256
#define IMG      1024
#define TILE_W   32
#define TILE_H   32
#define TILES_X  (IMG / TILE_W)    // 32
#define TILES_Y  (IMG / TILE_H)    // 32
#define FULL_EPS 1e-5f
#define BIG_AREA2 0.2f

#define LM_FLOATS   (NVERTS * 3)   // 1404 floats (5616 B)
#define TRI_INTS    (NTRI * 3)     // 768 ints   (3072 B)

typedef unsigned long long ull;

__device__ __forceinline__ ull pk2(float lo, float hi) {
    ull r;
    asm("mov.b64 %0, {%1, %2};" : "=l"(r) : "f"(lo), "f"(hi));
    return r;
}
__device__ __forceinline__ ull fma2(ull a, ull b, ull c) {
    ull d;
    asm("fma.rn.f32x2 %0, %1, %2, %3;" : "=l"(d) : "l"(a), "l"(b), "l"(c));
    return d;
}
__device__ __forceinline__ void upk2(ull v, int& lo, int& hi) {
    float a, b;
    asm("mov.b64 {%0, %1}, %2;" : "=f"(a), "=f"(b) : "l"(v));
    lo = __float_as_int(a);  hi = __float_as_int(b);
}

// --------------------------------------------------------------- fused ----
// One block per 32x32 tile (8192 blocks). R11 structure; the only change is
// __launch_bounds__(256, 8): force 32 regs -> 8 blocks/SM for latency hiding.
// Phase 0: stage landmarks+tri coalesced into smem (overlaid on coef arrays).
// Phase 1: thread t computes triangle t's edge coefs/bbox; full-cover vote;
//          ballot-compact into paired-edge layout (big-area first):
//            q0 = (A0,A1,C0,C1), q1 = (B0,B1,A2,B2), c2 = C2
// Phase 2: warp w owns rows [4w,4w+4); per triangle: edges 0,1 via one
//          fma.f32x2 per row, edge 2 scalar; sign-bit LOP3 coverage;
//          warp vote every 2 triangles (band-local early exit).
__global__ __launch_bounds__(256, 8)
void fused_kernel(const float* __restrict__ lm,
                  const int* __restrict__ tri,
                  float* __restrict__ out) {
    __shared__ __align__(16) char s_raw[NTRI * 32 + NTRI * 4];  // 8K + 1K
    __shared__ int s_offA[8], s_offB[8];
    __shared__ int s_cnt;

    float4 (*s_q)[2] = reinterpret_cast<float4(*)[2]>(s_raw);   // [NTRI][2]
    float*  s_c2     = reinterpret_cast<float*>(s_raw + NTRI * 32);
    float*  s_lmf    = reinterpret_cast<float*>(s_raw);
    int*    s_trii   = reinterpret_cast<int*>(s_raw + LM_FLOATS * 4);

    const int b   = blockIdx.z;
    const int t   = threadIdx.x;
    const int wid = t >> 5, lid = t & 31;

    // ---- Phase 0: coalesced staging ----
    {
        const float4* src = reinterpret_cast<const float4*>(lm + (size_t)b * LM_FLOATS);
        float4* dst = reinterpret_cast<float4*>(s_raw);
        for (int i = t; i < LM_FLOATS / 4; i += 256) dst[i] = src[i];
        const int4* tsrc = reinterpret_cast<const int4*>(tri);
        int4* tdst = reinterpret_cast<int4*>(s_raw + LM_FLOATS * 4);
        for (int i = t; i < TRI_INTS / 4; i += 256) tdst[i] = tsrc[i];
    }
    __syncthreads();

    // ---- Phase 1: per-triangle setup from smem ----
    const int i0 = s_trii[t * 3 + 0];
    const int i1 = s_trii[t * 3 + 1];
    const int i2 = s_trii[t * 3 + 2];
    const float ax = s_lmf[i0 * 3 + 0], ay = s_lmf[i0 * 3 + 1];
    const float bx = s_lmf[i1 * 3 + 0], by = s_lmf[i1 * 3 + 1];
    const float cx = s_lmf[i2 * 3 + 0], cy = s_lmf[i2 * 3 + 1];

    // edge(P,Q)(px,py) = -(Qy-Py)*px + (Qx-Px)*py + [(Qy-Py)*Px - (Qx-Px)*Py]
    float4 e0, e1, e2;
    { float dX = cx - bx, dY = cy - by;
      e0 = make_float4(-dY, dX, fmaf(dY, bx, -(dX * by)), 0.0f); }
    { float dX = ax - cx, dY = ay - cy;
      e1 = make_float4(-dY, dX, fmaf(dY, cx, -(dX * cy)), 0.0f); }
    { float dX = bx - ax, dY = by - ay;
      e2 = make_float4(-dY, dX, fmaf(dY, ax, -(dX * ay)), 0.0f); }

    // Tile extreme pixel centers: p = 1 - (idx + 0.5)/IMG
    const float pxmin = 1.0f - ((float)(blockIdx.x * TILE_W) + (TILE_W - 0.5f)) * (1.0f / IMG);
    const float pxmax = 1.0f - ((float)(blockIdx.x * TILE_W) + 0.5f)            * (1.0f / IMG);
    const float pymin = 1.0f - ((float)(blockIdx.y * TILE_H) + (TILE_H - 0.5f)) * (1.0f / IMG);
    const float pymax = 1.0f - ((float)(blockIdx.y * TILE_H) + 0.5f)            * (1.0f / IMG);

    const bool hit =
        (fminf(ax, fminf(bx, cx)) <= pxmax) && (fmaxf(ax, fmaxf(bx, cx)) >= pxmin) &&
        (fminf(ay, fminf(by, cy)) <= pymax) && (fmaxf(ay, fmaxf(by, cy)) >= pymin);

    bool full = false;
    if (hit) {
        float mn =  1e30f, mx = -1e30f;
        #pragma unroll
        for (int c = 0; c < 4; ++c) {
            const float cx_ = (c & 1) ? pxmax : pxmin;
            const float cy_ = (c & 2) ? pymax : pymin;
            const float w0 = fmaf(e0.x, cx_, fmaf(e0.y, cy_, e0.z));
            const float w1 = fmaf(e1.x, cx_, fmaf(e1.y, cy_, e1.z));
            const float w2 = fmaf(e2.x, cx_, fmaf(e2.y, cy_, e2.z));
            mn = fminf(mn, fminf(w0, fminf(w1, w2)));
            mx = fmaxf(mx, fmaxf(w0, fmaxf(w1, w2)));
        }
        full = (mn >= FULL_EPS) || (mx <= -FULL_EPS);
    }

    // Warp w owns rows [4w, 4w+4) of the tile; lane = column.
    const int x  = blockIdx.x * TILE_W + lid;
    const int y0 = blockIdx.y * TILE_H + wid * 4;
    const size_t obase = ((size_t)b << 20) + (size_t)y0 * IMG + x;

    // Barrier also fences staged-input reads before compaction overwrites.
    if (__syncthreads_or(full ? 1 : 0)) {   // tile fully covered
        out[obase]           = 1.0f;
        out[obase + IMG]     = 1.0f;
        out[obase + 2 * IMG] = 1.0f;
        out[obase + 3 * IMG] = 1.0f;
        return;
    }

    // Two-bucket compaction: big-area triangles first.
    const float area2 = fabsf((bx - ax) * (cy - ay) - (by - ay) * (cx - ax));
    const bool hA = hit && (area2 > BIG_AREA2);
    const bool hB = hit && !(area2 > BIG_AREA2);
    const unsigned mA = __ballot_sync(0xffffffffu, hA);
    const unsigned mB = __ballot_sync(0xffffffffu, hB);
    if (lid == 0) { s_offA[wid] = __popc(mA); s_offB[wid] = __popc(mB); }
    __syncthreads();
    if (t == 0) {
        int s = 0;
        #pragma unroll
        for (int i = 0; i < 8; ++i) { int c = s_offA[i]; s_offA[i] = s; s += c; }
        #pragma unroll
        for (int i = 0; i < 8; ++i) { int c = s_offB[i]; s_offB[i] = s; s += c; }
        s_cnt = s;
    }
    __syncthreads();
    const int posA = s_offA[wid] + __popc(mA & ((1u << lid) - 1u));
    const int posB = s_offB[wid] + __popc(mB & ((1u << lid) - 1u));
    const int pos  = hA ? posA : posB;
    if (hit) {
        s_q[pos][0] = make_float4(e0.x, e1.x, e0.z, e1.z);  // A0,A1,C0,C1
        s_q[pos][1] = make_float4(e0.y, e1.y, e2.x, e2.y);  // B0,B1,A2,B2
        s_c2[pos]   = e2.z;                                 // C2
    }
    __syncthreads();
    const int cnt = s_cnt;

    // ---- Phase 2: 4 contiguous rows/thread, paired-edge FFMA2 ----
    const float px = 1.0f - ((float)x + 0.5f) * (1.0f / IMG);
    const ull px2 = pk2(px, px);
    const float pyr0 = 1.0f - ((float)(y0 + 0) + 0.5f) * (1.0f / IMG);
    const float pyr1 = 1.0f - ((float)(y0 + 1) + 0.5f) * (1.0f / IMG);
    const float pyr2 = 1.0f - ((float)(y0 + 2) + 0.5f) * (1.0f / IMG);
    const float pyr3 = 1.0f - ((float)(y0 + 3) + 0.5f) * (1.0f / IMG);
    const ull pp0 = pk2(pyr0, pyr0), pp1 = pk2(pyr1, pyr1);
    const ull pp2 = pk2(pyr2, pyr2), pp3 = pk2(pyr3, pyr3);

    // n_r sign bit: 1 = not yet covered. Covered <=> n_r >= 0.
    int n0 = -1, n1 = -1, n2 = -1, n3 = -1;

#define TRI_TEST(T)                                                          \
    {   const float4 q0 = s_q[T][0];                                         \
        const float4 q1 = s_q[T][1];                                         \
        const float  c2v = s_c2[T];                                          \
        const ull A01 = pk2(q0.x, q0.y);                                     \
        const ull C01 = pk2(q0.z, q0.w);                                     \
        const ull B01 = pk2(q1.x, q1.y);                                     \
        const ull u01 = fma2(A01, px2, C01);                                 \
        const float u2 = fmaf(q1.z, px, c2v);                                \
        {   int a0, a1; upk2(fma2(B01, pp0, u01), a0, a1);                   \
            const int a2 = __float_as_int(fmaf(q1.w, pyr0, u2));             \
            n0 &= (a0 | a1 | a2) & ~(a0 & a1 & a2); }                        \
        {   int a0, a1; upk2(fma2(B01, pp1, u01), a0, a1);                   \
            const int a2 = __float_as_int(fmaf(q1.w, pyr1, u2));             \
            n1 &= (a0 | a1 | a2) & ~(a0 & a1 & a2); }                        \
        {   int a0, a1; upk2(fma2(B01, pp2, u01), a0, a1);                   \
            const int a2 = __float_as_int(fmaf(q1.w, pyr2, u2));             \
            n2 &= (a0 | a1 | a2) & ~(a0 & a1 & a2); }                        \
        {   int a0, a1; upk2(fma2(B01, pp3, u01), a0, a1);                   \
            const int a2 = __float_as_int(fmaf(q1.w, pyr3, u2));             \
            n3 &= (a0 | a1 | a2) & ~(a0 & a1 & a2); }                        \
    }

    int k = 0;
    #pragma unroll 1
    for (; k + 2 <= cnt; k += 2) {
        TRI_TEST(k)
        TRI_TEST(k + 1)
        if (__all_sync(0xffffffffu, (n0 | n1 | n2 | n3) >= 0)) break;
    }
    if (k + 1 == cnt) {       // odd remainder (only if no early exit)
        TRI_TEST(k)
    }
#undef TRI_TEST

    out[obase]           = (n0 >= 0) ? 1.0f : 0.0f;
    out[obase + IMG]     = (n1 >= 0) ? 1.0f : 0.0f;
    out[obase + 2 * IMG] = (n2 >= 0) ? 1.0f : 0.0f;
    out[obase + 3 * IMG] = (n3 >= 0) ? 1.0f : 0.0f;
}

// -------------------------------------------------------------- launch ----
extern "C" void kernel_launch(void* const* d_in, const int* in_sizes, int n_in,
                              void* d_out, int out_size) {
    const float* landmarks = (const float*)d_in[0];   // [8, 468, 3] f32
    const int*   tri       = (const int*)d_in[1];     // [256, 3] i32
    float* out = (float*)d_out;                       // [8, 1024, 1024] f32

    dim3 grid(TILES_X, TILES_Y, BATCH);               // 32 x 32 x 8 = 8192
    fused_kernel<<<grid, 256>>>(landmarks, tri, out);
}

// round 15
// speedup vs baseline: 1.0893x; 1.0893x over previous
#include <cuda_runtime.h>
#include <cuda_bf16.h>

#define BATCH    8
#define NVERTS   468
#define NTRI     256
#define IMG      1024
#define TILE_W   32
#define TILE_H   32
#define TILES_X  (IMG / TILE_W)    // 32
#define TILES_Y  (IMG / TILE_H)    // 32
#define FULL_EPS 1e-5f
#define BIG_AREA2 0.2f

#define LM_FLOATS   (NVERTS * 3)   // 1404 floats (5616 B)
#define TRI_INTS    (NTRI * 3)     // 768 ints   (3072 B)

typedef unsigned long long ull;

__device__ __forceinline__ ull pk2(float lo, float hi) {
    ull r;
    asm("mov.b64 %0, {%1, %2};" : "=l"(r) : "f"(lo), "f"(hi));
    return r;
}
__device__ __forceinline__ ull fma2(ull a, ull b, ull c) {
    ull d;
    asm("fma.rn.f32x2 %0, %1, %2, %3;" : "=l"(d) : "l"(a), "l"(b), "l"(c));
    return d;
}
__device__ __forceinline__ void upk2(ull v, int& lo, int& hi) {
    float a, b;
    asm("mov.b64 {%0, %1}, %2;" : "=f"(a), "=f"(b) : "l"(v));
    lo = __float_as_int(a);  hi = __float_as_int(b);
}

// --------------------------------------------------------------- fused ----
// One block per 32x32 tile (8192 blocks). R11 structure with two setup cuts:
//  - full-cover via sign-selected extreme corners (6 evals, not 12)
//  - compaction prefix computed by every thread (saves 1 barrier + serial scan)
__global__ __launch_bounds__(256)
void fused_kernel(const float* __restrict__ lm,
                  const int* __restrict__ tri,
                  float* __restrict__ out) {
    __shared__ __align__(16) char s_raw[NTRI * 32 + NTRI * 4];  // 8K + 1K
    __shared__ int s_woff[16];          // [0..7]=A popc, [8..15]=B popc

    float4 (*s_q)[2] = reinterpret_cast<float4(*)[2]>(s_raw);   // [NTRI][2]
    float*  s_c2     = reinterpret_cast<float*>(s_raw + NTRI * 32);
    float*  s_lmf    = reinterpret_cast<float*>(s_raw);
    int*    s_trii   = reinterpret_cast<int*>(s_raw + LM_FLOATS * 4);

    const int b   = blockIdx.z;
    const int t   = threadIdx.x;
    const int wid = t >> 5, lid = t & 31;

    // ---- Phase 0: coalesced staging ----
    {
        const float4* src = reinterpret_cast<const float4*>(lm + (size_t)b * LM_FLOATS);
        float4* dst = reinterpret_cast<float4*>(s_raw);
        for (int i = t; i < LM_FLOATS / 4; i += 256) dst[i] = src[i];
        const int4* tsrc = reinterpret_cast<const int4*>(tri);
        int4* tdst = reinterpret_cast<int4*>(s_raw + LM_FLOATS * 4);
        for (int i = t; i < TRI_INTS / 4; i += 256) tdst[i] = tsrc[i];
    }
    __syncthreads();

    // ---- Phase 1: per-triangle setup from smem ----
    const int i0 = s_trii[t * 3 + 0];
    const int i1 = s_trii[t * 3 + 1];
    const int i2 = s_trii[t * 3 + 2];
    const float ax = s_lmf[i0 * 3 + 0], ay = s_lmf[i0 * 3 + 1];
    const float bx = s_lmf[i1 * 3 + 0], by = s_lmf[i1 * 3 + 1];
    const float cx = s_lmf[i2 * 3 + 0], cy = s_lmf[i2 * 3 + 1];

    // edge(P,Q)(px,py) = -(Qy-Py)*px + (Qx-Px)*py + [(Qy-Py)*Px - (Qx-Px)*Py]
    float4 e0, e1, e2;
    { float dX = cx - bx, dY = cy - by;
      e0 = make_float4(-dY, dX, fmaf(dY, bx, -(dX * by)), 0.0f); }
    { float dX = ax - cx, dY = ay - cy;
      e1 = make_float4(-dY, dX, fmaf(dY, cx, -(dX * cy)), 0.0f); }
    { float dX = bx - ax, dY = by - ay;
      e2 = make_float4(-dY, dX, fmaf(dY, ax, -(dX * ay)), 0.0f); }

    // Tile extreme pixel centers: p = 1 - (idx + 0.5)/IMG
    const float pxmin = 1.0f - ((float)(blockIdx.x * TILE_W) + (TILE_W - 0.5f)) * (1.0f / IMG);
    const float pxmax = 1.0f - ((float)(blockIdx.x * TILE_W) + 0.5f)            * (1.0f / IMG);
    const float pymin = 1.0f - ((float)(blockIdx.y * TILE_H) + (TILE_H - 0.5f)) * (1.0f / IMG);
    const float pymax = 1.0f - ((float)(blockIdx.y * TILE_H) + 0.5f)            * (1.0f / IMG);

    const bool hit =
        (fminf(ax, fminf(bx, cx)) <= pxmax) && (fmaxf(ax, fmaxf(bx, cx)) >= pxmin) &&
        (fminf(ay, fminf(by, cy)) <= pymax) && (fmaxf(ay, fmaxf(by, cy)) >= pymin);

    // Full-cover via sign-selected extreme corners: affine w attains its
    // min/max over the tile rectangle at corners picked by sign(A), sign(B).
    bool full = false;
    if (hit) {
        float wmn =  1e30f, wmx = -1e30f;
        #pragma unroll
        for (int e = 0; e < 3; ++e) {
            const float4 E = (e == 0) ? e0 : (e == 1) ? e1 : e2;
            const float xlo = (E.x >= 0.0f) ? pxmin : pxmax;
            const float xhi = (E.x >= 0.0f) ? pxmax : pxmin;
            const float ylo = (E.y >= 0.0f) ? pymin : pymax;
            const float yhi = (E.y >= 0.0f) ? pymax : pymin;
            wmn = fminf(wmn, fmaf(E.x, xlo, fmaf(E.y, ylo, E.z)));
            wmx = fmaxf(wmx, fmaf(E.x, xhi, fmaf(E.y, yhi, E.z)));
        }
        full = (wmn >= FULL_EPS) || (wmx <= -FULL_EPS);
    }

    // Warp w owns rows [4w, 4w+4) of the tile; lane = column.
    const int x  = blockIdx.x * TILE_W + lid;
    const int y0 = blockIdx.y * TILE_H + wid * 4;
    const size_t obase = ((size_t)b << 20) + (size_t)y0 * IMG + x;

    // Barrier also fences staged-input reads before compaction overwrites.
    if (__syncthreads_or(full ? 1 : 0)) {   // tile fully covered
        out[obase]           = 1.0f;
        out[obase + IMG]     = 1.0f;
        out[obase + 2 * IMG] = 1.0f;
        out[obase + 3 * IMG] = 1.0f;
        return;
    }

    // Two-bucket compaction: big-area triangles first.
    const float area2 = fabsf((bx - ax) * (cy - ay) - (by - ay) * (cx - ax));
    const bool hA = hit && (area2 > BIG_AREA2);
    const bool hB = hit && !(area2 > BIG_AREA2);
    const unsigned mA = __ballot_sync(0xffffffffu, hA);
    const unsigned mB = __ballot_sync(0xffffffffu, hB);
    if (lid == 0) { s_woff[wid] = __popc(mA); s_woff[8 + wid] = __popc(mB); }
    __syncthreads();

    // Every thread computes its own prefix + total (broadcast LDS reads).
    int baseA = 0, baseB = 0, cnt = 0;
    {
        int c[16];
        #pragma unroll
        for (int i = 0; i < 16; ++i) c[i] = s_woff[i];
        #pragma unroll
        for (int i = 0; i < 8; ++i) {       // A bucket prefix
            if (i < wid) baseA += c[i];
            cnt += c[i];
        }
        baseB = cnt;                        // B starts after all of A
        #pragma unroll
        for (int i = 0; i < 8; ++i) {       // B bucket prefix
            if (i < wid) baseB += c[8 + i];
            cnt += c[8 + i];
        }
    }
    const int pos = hA ? (baseA + __popc(mA & ((1u << lid) - 1u)))
                       : (baseB + __popc(mB & ((1u << lid) - 1u)));
    if (hit) {
        s_q[pos][0] = make_float4(e0.x, e1.x, e0.z, e1.z);  // A0,A1,C0,C1
        s_q[pos][1] = make_float4(e0.y, e1.y, e2.x, e2.y);  // B0,B1,A2,B2
        s_c2[pos]   = e2.z;                                 // C2
    }
    __syncthreads();

    // ---- Phase 2: 4 contiguous rows/thread, paired-edge FFMA2 ----
    const float px = 1.0f - ((float)x + 0.5f) * (1.0f / IMG);
    const ull px2 = pk2(px, px);
    const float pyr0 = 1.0f - ((float)(y0 + 0) + 0.5f) * (1.0f / IMG);
    const float pyr1 = 1.0f - ((float)(y0 + 1) + 0.5f) * (1.0f / IMG);
    const float pyr2 = 1.0f - ((float)(y0 + 2) + 0.5f) * (1.0f / IMG);
    const float pyr3 = 1.0f - ((float)(y0 + 3) + 0.5f) * (1.0f / IMG);
    const ull pp0 = pk2(pyr0, pyr0), pp1 = pk2(pyr1, pyr1);
    const ull pp2 = pk2(pyr2, pyr2), pp3 = pk2(pyr3, pyr3);

    // n_r sign bit: 1 = not yet covered. Covered <=> n_r >= 0.
    int n0 = -1, n1 = -1, n2 = -1, n3 = -1;

#define TRI_TEST(T)                                                          \
    {   const float4 q0 = s_q[T][0];                                         \
        const float4 q1 = s_q[T][1];                                         \
        const float  c2v = s_c2[T];                                          \
        const ull A01 = pk2(q0.x, q0.y);                                     \
        const ull C01 = pk2(q0.z, q0.w);                                     \
        const ull B01 = pk2(q1.x, q1.y);                                     \
        const ull u01 = fma2(A01, px2, C01);                                 \
        const float u2 = fmaf(q1.z, px, c2v);                                \
        {   int a0, a1; upk2(fma2(B01, pp0, u01), a0, a1);                   \
            const int a2 = __float_as_int(fmaf(q1.w, pyr0, u2));             \
            n0 &= (a0 | a1 | a2) & ~(a0 & a1 & a2); }                        \
        {   int a0, a1; upk2(fma2(B01, pp1, u01), a0, a1);                   \
            const int a2 = __float_as_int(fmaf(q1.w, pyr1, u2));             \
            n1 &= (a0 | a1 | a2) & ~(a0 & a1 & a2); }                        \
        {   int a0, a1; upk2(fma2(B01, pp2, u01), a0, a1);                   \
            const int a2 = __float_as_int(fmaf(q1.w, pyr2, u2));             \
            n2 &= (a0 | a1 | a2) & ~(a0 & a1 & a2); }                        \
        {   int a0, a1; upk2(fma2(B01, pp3, u01), a0, a1);                   \
            const int a2 = __float_as_int(fmaf(q1.w, pyr3, u2));             \
            n3 &= (a0 | a1 | a2) & ~(a0 & a1 & a2); }                        \
    }

    int k = 0;
    #pragma unroll 1
    for (; k + 2 <= cnt; k += 2) {
        TRI_TEST(k)
        TRI_TEST(k + 1)
        if (__all_sync(0xffffffffu, (n0 | n1 | n2 | n3) >= 0)) break;
    }
    if (k + 1 == cnt) {       // odd remainder (only if no early exit)
        TRI_TEST(k)
    }
#undef TRI_TEST

    out[obase]           = (n0 >= 0) ? 1.0f : 0.0f;
    out[obase + IMG]     = (n1 >= 0) ? 1.0f : 0.0f;
    out[obase + 2 * IMG] = (n2 >= 0) ? 1.0f : 0.0f;
    out[obase + 3 * IMG] = (n3 >= 0) ? 1.0f : 0.0f;
}

// -------------------------------------------------------------- launch ----
extern "C" void kernel_launch(void* const* d_in, const int* in_sizes, int n_in,
                              void* d_out, int out_size) {
    const float* landmarks = (const float*)d_in[0];   // [8, 468, 3] f32
    const int*   tri       = (const int*)d_in[1];     // [256, 3] i32
    float* out = (float*)d_out;                       // [8, 1024, 1024] f32

    dim3 grid(TILES_X, TILES_Y, BATCH);               // 32 x 32 x 8 = 8192
    fused_kernel<<<grid, 256>>>(landmarks, tri, out);
}

// round 16
// speedup vs baseline: 1.1534x; 1.0588x over previous
#include <cuda_runtime.h>
#include <cuda_bf16.h>

#define BATCH    8
#define NVERTS   468
#define NTRI     256
#define IMG      1024
#define TILE_W   32
#define TILE_H   32
#define TILES_X  (IMG / TILE_W)    // 32
#define TILES_Y  (IMG / TILE_H)    // 32
#define FULL_EPS 1e-5f
#define BIG_AREA2 0.2f

typedef unsigned long long ull;

__device__ __forceinline__ ull pk2(float lo, float hi) {
    ull r;
    asm("mov.b64 %0, {%1, %2};" : "=l"(r) : "f"(lo), "f"(hi));
    return r;
}
__device__ __forceinline__ ull fma2(ull a, ull b, ull c) {
    ull d;
    asm("fma.rn.f32x2 %0, %1, %2, %3;" : "=l"(d) : "l"(a), "l"(b), "l"(c));
    return d;
}
__device__ __forceinline__ void upk2(ull v, int& lo, int& hi) {
    float a, b;
    asm("mov.b64 {%0, %1}, %2;" : "=f"(a), "=f"(b) : "l"(v));
    lo = __float_as_int(a);  hi = __float_as_int(b);
}

// --------------------------------------------------------------- fused ----
// One block per 32x32 tile (8192 blocks). R11 structure; changes vs R11:
//  - stage landmarks as float2 (x,y) only -> vertex gather = 3 LDS.64
//  - tri[] read directly via coalesced LDG (no smem staging)
// Loop / vote / compaction identical to the 31.5us best.
__global__ __launch_bounds__(256)
void fused_kernel(const float* __restrict__ lm,
                  const int* __restrict__ tri,
                  float* __restrict__ out) {
    __shared__ __align__(16) char s_raw[NTRI * 32 + NTRI * 4];  // 8K + 1K
    __shared__ int s_offA[8], s_offB[8];
    __shared__ int s_cnt;

    float4 (*s_q)[2] = reinterpret_cast<float4(*)[2]>(s_raw);   // [NTRI][2]
    float*  s_c2     = reinterpret_cast<float*>(s_raw + NTRI * 32);
    float2* s_lm2    = reinterpret_cast<float2*>(s_raw);        // staging overlay

    const int b   = blockIdx.z;
    const int t   = threadIdx.x;
    const int wid = t >> 5, lid = t & 31;

    // ---- Phase 0: stage landmark (x,y) pairs; tri not staged ----
    {
        const float* base = lm + (size_t)b * NVERTS * 3;
        #pragma unroll
        for (int v = t; v < NVERTS; v += 256)
            s_lm2[v] = make_float2(base[v * 3 + 0], base[v * 3 + 1]);
    }
    // tri gather: coalesced LDG (warp reads 96 consecutive words)
    const int i0 = __ldg(tri + t * 3 + 0);
    const int i1 = __ldg(tri + t * 3 + 1);
    const int i2 = __ldg(tri + t * 3 + 2);
    __syncthreads();

    // ---- Phase 1: per-triangle setup (3 LDS.64 gather) ----
    const float2 va = s_lm2[i0];
    const float2 vb = s_lm2[i1];
    const float2 vc = s_lm2[i2];
    const float ax = va.x, ay = va.y;
    const float bx = vb.x, by = vb.y;
    const float cx = vc.x, cy = vc.y;

    // edge(P,Q)(px,py) = -(Qy-Py)*px + (Qx-Px)*py + [(Qy-Py)*Px - (Qx-Px)*Py]
    float4 e0, e1, e2;
    { float dX = cx - bx, dY = cy - by;
      e0 = make_float4(-dY, dX, fmaf(dY, bx, -(dX * by)), 0.0f); }
    { float dX = ax - cx, dY = ay - cy;
      e1 = make_float4(-dY, dX, fmaf(dY, cx, -(dX * cy)), 0.0f); }
    { float dX = bx - ax, dY = by - ay;
      e2 = make_float4(-dY, dX, fmaf(dY, ax, -(dX * ay)), 0.0f); }

    // Tile extreme pixel centers: p = 1 - (idx + 0.5)/IMG
    const float pxmin = 1.0f - ((float)(blockIdx.x * TILE_W) + (TILE_W - 0.5f)) * (1.0f / IMG);
    const float pxmax = 1.0f - ((float)(blockIdx.x * TILE_W) + 0.5f)            * (1.0f / IMG);
    const float pymin = 1.0f - ((float)(blockIdx.y * TILE_H) + (TILE_H - 0.5f)) * (1.0f / IMG);
    const float pymax = 1.0f - ((float)(blockIdx.y * TILE_H) + 0.5f)            * (1.0f / IMG);

    const bool hit =
        (fminf(ax, fminf(bx, cx)) <= pxmax) && (fmaxf(ax, fmaxf(bx, cx)) >= pxmin) &&
        (fminf(ay, fminf(by, cy)) <= pymax) && (fmaxf(ay, fmaxf(by, cy)) >= pymin);

    bool full = false;
    if (hit) {
        float mn =  1e30f, mx = -1e30f;
        #pragma unroll
        for (int c = 0; c < 4; ++c) {
            const float cx_ = (c & 1) ? pxmax : pxmin;
            const float cy_ = (c & 2) ? pymax : pymin;
            const float w0 = fmaf(e0.x, cx_, fmaf(e0.y, cy_, e0.z));
            const float w1 = fmaf(e1.x, cx_, fmaf(e1.y, cy_, e1.z));
            const float w2 = fmaf(e2.x, cx_, fmaf(e2.y, cy_, e2.z));
            mn = fminf(mn, fminf(w0, fminf(w1, w2)));
            mx = fmaxf(mx, fmaxf(w0, fmaxf(w1, w2)));
        }
        full = (mn >= FULL_EPS) || (mx <= -FULL_EPS);
    }

    // Warp w owns rows [4w, 4w+4) of the tile; lane = column.
    const int x  = blockIdx.x * TILE_W + lid;
    const int y0 = blockIdx.y * TILE_H + wid * 4;
    const size_t obase = ((size_t)b << 20) + (size_t)y0 * IMG + x;

    // Barrier also fences staged-input reads before compaction overwrites.
    if (__syncthreads_or(full ? 1 : 0)) {   // tile fully covered
        out[obase]           = 1.0f;
        out[obase + IMG]     = 1.0f;
        out[obase + 2 * IMG] = 1.0f;
        out[obase + 3 * IMG] = 1.0f;
        return;
    }

    // Two-bucket compaction: big-area triangles first.
    const float area2 = fabsf((bx - ax) * (cy - ay) - (by - ay) * (cx - ax));
    const bool hA = hit && (area2 > BIG_AREA2);
    const bool hB = hit && !(area2 > BIG_AREA2);
    const unsigned mA = __ballot_sync(0xffffffffu, hA);
    const unsigned mB = __ballot_sync(0xffffffffu, hB);
    if (lid == 0) { s_offA[wid] = __popc(mA); s_offB[wid] = __popc(mB); }
    __syncthreads();
    if (t == 0) {
        int s = 0;
        #pragma unroll
        for (int i = 0; i < 8; ++i) { int c = s_offA[i]; s_offA[i] = s; s += c; }
        #pragma unroll
        for (int i = 0; i < 8; ++i) { int c = s_offB[i]; s_offB[i] = s; s += c; }
        s_cnt = s;
    }
    __syncthreads();
    const int posA = s_offA[wid] + __popc(mA & ((1u << lid) - 1u));
    const int posB = s_offB[wid] + __popc(mB & ((1u << lid) - 1u));
    const int pos  = hA ? posA : posB;
    if (hit) {
        s_q[pos][0] = make_float4(e0.x, e1.x, e0.z, e1.z);  // A0,A1,C0,C1
        s_q[pos][1] = make_float4(e0.y, e1.y, e2.x, e2.y);  // B0,B1,A2,B2
        s_c2[pos]   = e2.z;                                 // C2
    }
    __syncthreads();
    const int cnt = s_cnt;

    // ---- Phase 2: 4 contiguous rows/thread, paired-edge FFMA2 ----
    const float px = 1.0f - ((float)x + 0.5f) * (1.0f / IMG);
    const ull px2 = pk2(px, px);
    const float pyr0 = 1.0f - ((float)(y0 + 0) + 0.5f) * (1.0f / IMG);
    const float pyr1 = 1.0f - ((float)(y0 + 1) + 0.5f) * (1.0f / IMG);
    const float pyr2 = 1.0f - ((float)(y0 + 2) + 0.5f) * (1.0f / IMG);
    const float pyr3 = 1.0f - ((float)(y0 + 3) + 0.5f) * (1.0f / IMG);
    const ull pp0 = pk2(pyr0, pyr0), pp1 = pk2(pyr1, pyr1);
    const ull pp2 = pk2(pyr2, pyr2), pp3 = pk2(pyr3, pyr3);

    // n_r sign bit: 1 = not yet covered. Covered <=> n_r >= 0.
    int n0 = -1, n1 = -1, n2 = -1, n3 = -1;

#define TRI_TEST(T)                                                          \
    {   const float4 q0 = s_q[T][0];                                         \
        const float4 q1 = s_q[T][1];                                         \
        const float  c2v = s_c2[T];                                          \
        const ull A01 = pk2(q0.x, q0.y);                                     \
        const ull C01 = pk2(q0.z, q0.w);                                     \
        const ull B01 = pk2(q1.x, q1.y);                                     \
        const ull u01 = fma2(A01, px2, C01);                                 \
        const float u2 = fmaf(q1.z, px, c2v);                                \
        {   int a0, a1; upk2(fma2(B01, pp0, u01), a0, a1);                   \
            const int a2 = __float_as_int(fmaf(q1.w, pyr0, u2));             \
            n0 &= (a0 | a1 | a2) & ~(a0 & a1 & a2); }                        \
        {   int a0, a1; upk2(fma2(B01, pp1, u01), a0, a1);                   \
            const int a2 = __float_as_int(fmaf(q1.w, pyr1, u2));             \
            n1 &= (a0 | a1 | a2) & ~(a0 & a1 & a2); }                        \
        {   int a0, a1; upk2(fma2(B01, pp2, u01), a0, a1);                   \
            const int a2 = __float_as_int(fmaf(q1.w, pyr2, u2));             \
            n2 &= (a0 | a1 | a2) & ~(a0 & a1 & a2); }                        \
        {   int a0, a1; upk2(fma2(B01, pp3, u01), a0, a1);                   \
            const int a2 = __float_as_int(fmaf(q1.w, pyr3, u2));             \
            n3 &= (a0 | a1 | a2) & ~(a0 & a1 & a2); }                        \
    }

    int k = 0;
    #pragma unroll 1
    for (; k + 2 <= cnt; k += 2) {
        TRI_TEST(k)
        TRI_TEST(k + 1)
        if (__all_sync(0xffffffffu, (n0 | n1 | n2 | n3) >= 0)) break;
    }
    if (k + 1 == cnt) {       // odd remainder (only if no early exit)
        TRI_TEST(k)
    }
#undef TRI_TEST

    out[obase]           = (n0 >= 0) ? 1.0f : 0.0f;
    out[obase + IMG]     = (n1 >= 0) ? 1.0f : 0.0f;
    out[obase + 2 * IMG] = (n2 >= 0) ? 1.0f : 0.0f;
    out[obase + 3 * IMG] = (n3 >= 0) ? 1.0f : 0.0f;
}

// -------------------------------------------------------------- launch ----
extern "C" void kernel_launch(void* const* d_in, const int* in_sizes, int n_in,
                              void* d_out, int out_size) {
    const float* landmarks = (const float*)d_in[0];   // [8, 468, 3] f32
    const int*   tri       = (const int*)d_in[1];     // [256, 3] i32
    float* out = (float*)d_out;                       // [8, 1024, 1024] f32

    dim3 grid(TILES_X, TILES_Y, BATCH);               // 32 x 32 x 8 = 8192
    fused_kernel<<<grid, 256>>>(landmarks, tri, out);
}